// round 10
// baseline (speedup 1.0000x reference)
#include <cuda_runtime.h>
#include <math.h>
#include <stdint.h>

#define N 8192
#define CLS 8
#define DIM 256
#define INV_T 14.285714285714286f
#define EXP_SCALE 20.60992915555662f   /* (1/0.07) * log2(e) */
#define ALPHA 0.3f
#define LSM 0.1f
#define NT_ROW 64
#define NCHUNK 128
#define GRID 148
#define NWARPS (GRID * 16)             /* 2368 global warps */

// ---------------- scratch ------------------------------------------------------------
__device__ float g_embn[N * DIM];
__device__ uint16_t g_embq[N * DIM / 2];
__device__ float g_clsum_part[NCHUNK * CLS * DIM];
__device__ float g_clcnt_part[NCHUNK * CLS];
__device__ float g_clsum[CLS * DIM];
__device__ float g_clcnt[CLS];
__device__ float g_Zp[N * NT_ROW];
__device__ float g_con_part[NWARPS];
__device__ float g_ce_part[N / 32];
__device__ unsigned g_bar_cnt[8];
__device__ unsigned g_bar_gen[8];

// ---------------- helpers ------------------------------------------------------------
__device__ __forceinline__ uint32_t smem_u32(const void* p) {
    uint32_t a;
    asm("{ .reg .u64 t; cvta.to.shared.u64 t, %1; cvt.u32.u64 %0, t; }" : "=r"(a) : "l"(p));
    return a;
}
__device__ __forceinline__ float ex2f(float x) {
    float y; asm("ex2.approx.f32 %0, %1;" : "=f"(y) : "f"(x)); return y;
}
__device__ __forceinline__ void cp16(uint32_t dst, const void* src) {
    asm volatile("cp.async.cg.shared.global [%0], [%1], 16;" :: "r"(dst), "l"(src));
}
#define CP_COMMIT() asm volatile("cp.async.commit_group;" ::: "memory")
#define CP_WAIT0()  asm volatile("cp.async.wait_group 0;" ::: "memory")

__device__ __forceinline__ void ldsm4(uint32_t& r0, uint32_t& r1, uint32_t& r2, uint32_t& r3,
                                      uint32_t addr) {
    asm volatile("ldmatrix.sync.aligned.m8n8.x4.shared.b16 {%0,%1,%2,%3}, [%4];"
                 : "=r"(r0), "=r"(r1), "=r"(r2), "=r"(r3) : "r"(addr));
}
__device__ __forceinline__ void mma_fp8(float* c, uint32_t a0, uint32_t a1, uint32_t a2,
                                        uint32_t a3, uint32_t b0, uint32_t b1) {
    asm volatile("mma.sync.aligned.m16n8k32.row.col.f32.e4m3.e4m3.f32 "
                 "{%0,%1,%2,%3}, {%4,%5,%6,%7}, {%8,%9}, {%0,%1,%2,%3};"
                 : "+f"(c[0]), "+f"(c[1]), "+f"(c[2]), "+f"(c[3])
                 : "r"(a0), "r"(a1), "r"(a2), "r"(a3), "r"(b0), "r"(b1));
}
__device__ __forceinline__ uint16_t f2e4m3x2(float hi, float lo) {
    uint16_t r;
    asm("cvt.rn.satfinite.e4m3x2.f32 %0, %1, %2;" : "=h"(r) : "f"(hi), "f"(lo));
    return r;
}

// device-wide sense-free barrier (monotonic generation; graph-replay safe)
__device__ __forceinline__ void grid_barrier(int k) {
    __syncthreads();
    if (threadIdx.x == 0) {
        __threadfence();
        unsigned gen = g_bar_gen[k];
        unsigned t = atomicAdd(&g_bar_cnt[k], 1u);
        if (t == GRID - 1) {
            g_bar_cnt[k] = 0;
            __threadfence();
            atomicAdd(&g_bar_gen[k], 1u);
        } else {
            while (((volatile unsigned*)g_bar_gen)[k] == gen) __nanosleep(64);
            __threadfence();
        }
    }
    __syncthreads();
}

// ---------------- the one kernel -----------------------------------------------------
#define SAB 272
#define A_BYTES (128 * SAB)
#define AS(p) ((p) * A_BYTES)
#define BS(b) ((2 + (b)) * A_BYTES)
#define RED_OFF (4 * A_BYTES)            /* 139264 */
#define RED_PAR 4096
#define SMEM_TOTAL (RED_OFF + 2 * RED_PAR)

__device__ __forceinline__ void load_tile_async(uint32_t sbase, int grow0, int tid) {
    const char* src = (const char*)g_embq + (size_t)grow0 * 256;
#pragma unroll
    for (int i = 0; i < 4; i++) {
        int idx = tid + i * 512;
        int row = idx >> 4, cb = idx & 15;
        cp16(sbase + row * SAB + cb * 16, src + (size_t)row * 256 + cb * 16);
    }
}

__global__ void __launch_bounds__(512, 1) k_all(const float* __restrict__ logits,
                                                const float* __restrict__ emb,
                                                const int* __restrict__ tgt,
                                                float* __restrict__ out, int out_size) {
    extern __shared__ char smem[];
    uint32_t sb = smem_u32(smem);
    int tid = threadIdx.x;
    int lane = tid & 31;
    int wid = tid >> 5;
    int bid = blockIdx.x;
    int gw = bid * 16 + wid;            // global warp id

    // ================= phase 0: normalize + focal-CE =================
    for (int row = gw; row < N; row += NWARPS) {
        const float4* src = (const float4*)(emb + (size_t)row * DIM);
        float4 v0 = src[lane * 2], v1 = src[lane * 2 + 1];
        float ss = v0.x * v0.x + v0.y * v0.y + v0.z * v0.z + v0.w * v0.w +
                   v1.x * v1.x + v1.y * v1.y + v1.z * v1.z + v1.w * v1.w;
#pragma unroll
        for (int off = 16; off > 0; off >>= 1) ss += __shfl_xor_sync(0xFFFFFFFF, ss, off);
        float inv = 1.0f / fmaxf(sqrtf(ss), 1e-12f);
        v0.x *= inv; v0.y *= inv; v0.z *= inv; v0.w *= inv;
        v1.x *= inv; v1.y *= inv; v1.z *= inv; v1.w *= inv;
        float4* dst = (float4*)(g_embn + (size_t)row * DIM);
        dst[lane * 2] = v0;
        dst[lane * 2 + 1] = v1;
        uint32_t u0 = (uint32_t)f2e4m3x2(v0.y, v0.x) | ((uint32_t)f2e4m3x2(v0.w, v0.z) << 16);
        uint32_t u1 = (uint32_t)f2e4m3x2(v1.y, v1.x) | ((uint32_t)f2e4m3x2(v1.w, v1.z) << 16);
        *(uint2*)(g_embq + (size_t)row * 128 + lane * 4) = make_uint2(u0, u1);
    }
    {   // focal-CE: first 8192 global threads, one row each
        int g = bid * 512 + tid;
        if (g < N) {
            const float4* p = (const float4*)(logits + (size_t)g * CLS);
            float4 u = p[0], w = p[1];
            float x[CLS] = {u.x, u.y, u.z, u.w, w.x, w.y, w.z, w.w};
            float m = x[0];
#pragma unroll
            for (int j = 1; j < CLS; j++) m = fmaxf(m, x[j]);
            float se = 0.f;
#pragma unroll
            for (int j = 0; j < CLS; j++) se += expf(x[j] - m);
            float lse = m + logf(se);
            int tg = tgt[g];
            float nll = lse - x[tg];
            float sx = 0.f;
#pragma unroll
            for (int j = 0; j < CLS; j++) sx += x[j];
            float smooth = lse - sx * (1.0f / CLS);
            float ce = (1.0f - LSM) * nll + LSM * smooth;
            float pt = expf(-ce);
            float omp = 1.0f - pt;
            float focal = omp * omp * ce;
#pragma unroll
            for (int off = 16; off > 0; off >>= 1)
                focal += __shfl_xor_sync(0xFFFFFFFF, focal, off);
            if (lane == 0) g_ce_part[g >> 5] = focal;
        }
    }
    grid_barrier(0);

    // ================= phase 1: symmetric Z + class-sum side jobs =================
    {
        int wx = wid & 3;
        int wy = wid >> 2;
        int base = bid * 14 + (bid < 8 ? bid : 8);
        int cnt = 14 + (bid < 8 ? 1 : 0);

        int idx = base, I = 0;
        while (idx >= NT_ROW - I) { idx -= NT_ROW - I; I++; }
        int J = I + idx;

        int ap = 0;
        load_tile_async(sb + AS(0), I * 128, tid);
        if (J != I) load_tile_async(sb + BS(0), J * 128, tid);
        CP_COMMIT();

        // class-sum partials on CTAs 8..71 (no-side-job CTAs are the critical 15-tile ones)
        if (bid >= 8 && bid < 72) {
            int half = tid >> 8;
            int d = tid & 255;
            int chunk = (bid - 8) * 2 + half;
            int i0 = chunk * 64;
            float a[CLS];
#pragma unroll
            for (int c = 0; c < CLS; c++) a[c] = 0.f;
            for (int k = 0; k < 64; k++) {
                int tg = tgt[i0 + k];
                float v = g_embn[(size_t)(i0 + k) * DIM + d];
#pragma unroll
                for (int c = 0; c < CLS; c++) a[c] += (tg == c) ? v : 0.f;
            }
#pragma unroll
            for (int c = 0; c < CLS; c++) g_clsum_part[(chunk * CLS + c) * DIM + d] = a[c];
            if (d == 0) {
                int cc[CLS];
#pragma unroll
                for (int c = 0; c < CLS; c++) cc[c] = 0;
                for (int k = 0; k < 64; k++) {
                    int tg = tgt[i0 + k];
#pragma unroll
                    for (int c = 0; c < CLS; c++) cc[c] += (tg == c);
                }
#pragma unroll
                for (int c = 0; c < CLS; c++) g_clcnt_part[chunk * CLS + c] = (float)cc[c];
            }
        }

        CP_WAIT0();
        __syncthreads();

        uint32_t a_lane = (wy * 32 + (lane & 15)) * SAB + ((lane >> 4) << 4);
        uint32_t b_lane = ((lane & 7) + ((lane >> 4) << 3)) * SAB + (((lane >> 3) & 1) << 4) +
                          (wx * 32) * SAB;

        const float EXP_DIAG = expf(INV_T);
        int lrl0 = wy * 32 + (lane >> 2);
        int lcb0 = wx * 32 + (lane & 3) * 2;

        float prev[2][4][4];
        int Ip = 0, Jp = 0;
        bool dtp = false;

        for (int t = 0; t < cnt; t++) {
            int I1 = I, J1 = J + 1;
            if (J1 == NT_ROW) { I1 = I + 1; J1 = I1; }
            bool havenext = (t + 1 < cnt);
            int apn = ap;
            if (havenext) {
                if (I1 != I) {
                    apn = ap ^ 1;
                    load_tile_async(sb + AS(apn), I1 * 128, tid);
                }
                if (J1 != I1) {
                    load_tile_async(sb + BS((t + 1) & 1), J1 * 128, tid);
                }
                CP_COMMIT();
            }

            bool dt = (I == J);
            uint32_t a_addr = sb + AS(ap) + a_lane;
            uint32_t bbuf = (dt ? (sb + AS(ap)) : (sb + BS(t & 1))) + b_lane;

            float acc[2][4][4];
#pragma unroll
            for (int mt = 0; mt < 2; mt++)
#pragma unroll
                for (int nt = 0; nt < 4; nt++)
#pragma unroll
                    for (int q = 0; q < 4; q++) acc[mt][nt][q] = 0.f;

            float rlo[2] = {0.f, 0.f}, rhi[2] = {0.f, 0.f};
            float cp0[4] = {0.f, 0.f, 0.f, 0.f}, cp1[4] = {0.f, 0.f, 0.f, 0.f};

#pragma unroll
            for (int ks = 0; ks < 8; ks++) {
                uint32_t koff = ks * 32;
                uint32_t a0[4], a1[4];
                ldsm4(a0[0], a0[1], a0[2], a0[3], a_addr + koff);
                ldsm4(a1[0], a1[1], a1[2], a1[3], a_addr + 16 * SAB + koff);
                uint32_t bfr[2][4];
#pragma unroll
                for (int p = 0; p < 2; p++)
                    ldsm4(bfr[p][0], bfr[p][1], bfr[p][2], bfr[p][3],
                          bbuf + (p * 16) * SAB + koff);
#pragma unroll
                for (int nt = 0; nt < 4; nt++) {
                    uint32_t bb0 = bfr[nt >> 1][(nt & 1) * 2];
                    uint32_t bb1 = bfr[nt >> 1][(nt & 1) * 2 + 1];
                    mma_fp8(acc[0][nt], a0[0], a0[1], a0[2], a0[3], bb0, bb1);
                    mma_fp8(acc[1][nt], a1[0], a1[1], a1[2], a1[3], bb0, bb1);
                }
                if (t > 0) {
                    int mt = ks & 1, nt = ks >> 1;
                    int lr = lrl0 + mt * 16;
                    int lc = lcb0 + nt * 8;
                    float v0 = (dtp && lc == lr)         ? EXP_DIAG : ex2f(prev[mt][nt][0] * EXP_SCALE);
                    float v1 = (dtp && lc + 1 == lr)     ? EXP_DIAG : ex2f(prev[mt][nt][1] * EXP_SCALE);
                    float v2 = (dtp && lc == lr + 8)     ? EXP_DIAG : ex2f(prev[mt][nt][2] * EXP_SCALE);
                    float v3 = (dtp && lc + 1 == lr + 8) ? EXP_DIAG : ex2f(prev[mt][nt][3] * EXP_SCALE);
                    rlo[mt] += v0 + v1;
                    rhi[mt] += v2 + v3;
                    cp0[nt] += v0 + v2;
                    cp1[nt] += v1 + v3;
                }
            }

            if (t > 0) {
                float* red_row = (float*)(smem + RED_OFF + ((t - 1) & 1) * RED_PAR);
                float* red_col = red_row + 512;
#pragma unroll
                for (int mt = 0; mt < 2; mt++) {
                    rlo[mt] += __shfl_xor_sync(0xFFFFFFFF, rlo[mt], 1);
                    rlo[mt] += __shfl_xor_sync(0xFFFFFFFF, rlo[mt], 2);
                    rhi[mt] += __shfl_xor_sync(0xFFFFFFFF, rhi[mt], 1);
                    rhi[mt] += __shfl_xor_sync(0xFFFFFFFF, rhi[mt], 2);
                }
#pragma unroll
                for (int nt = 0; nt < 4; nt++) {
                    cp0[nt] += __shfl_xor_sync(0xFFFFFFFF, cp0[nt], 4);
                    cp0[nt] += __shfl_xor_sync(0xFFFFFFFF, cp0[nt], 8);
                    cp0[nt] += __shfl_xor_sync(0xFFFFFFFF, cp0[nt], 16);
                    cp1[nt] += __shfl_xor_sync(0xFFFFFFFF, cp1[nt], 4);
                    cp1[nt] += __shfl_xor_sync(0xFFFFFFFF, cp1[nt], 8);
                    cp1[nt] += __shfl_xor_sync(0xFFFFFFFF, cp1[nt], 16);
                }
                if ((lane & 3) == 0) {
#pragma unroll
                    for (int mt = 0; mt < 2; mt++) {
                        int r = wy * 32 + mt * 16 + (lane >> 2);
                        red_row[r * 4 + wx] = rlo[mt];
                        red_row[(r + 8) * 4 + wx] = rhi[mt];
                    }
                }
                if (lane < 4) {
#pragma unroll
                    for (int nt = 0; nt < 4; nt++) {
                        int c = wx * 32 + nt * 8 + lane * 2;
                        red_col[c * 4 + wy] = cp0[nt];
                        red_col[(c + 1) * 4 + wy] = cp1[nt];
                    }
                }
            }
            if (havenext) CP_WAIT0();
            __syncthreads();
            if (t > 0 && tid < 128) {
                float* red_row = (float*)(smem + RED_OFF + ((t - 1) & 1) * RED_PAR);
                float* red_col = red_row + 512;
                float rz = (red_row[tid * 4] + red_row[tid * 4 + 1]) +
                           (red_row[tid * 4 + 2] + red_row[tid * 4 + 3]);
                g_Zp[(size_t)(Ip * 128 + tid) * NT_ROW + Jp] = rz;
                if (!dtp) {
                    float cz = (red_col[tid * 4] + red_col[tid * 4 + 1]) +
                               (red_col[tid * 4 + 2] + red_col[tid * 4 + 3]);
                    g_Zp[(size_t)(Jp * 128 + tid) * NT_ROW + Ip] = cz;
                }
            }

#pragma unroll
            for (int mt = 0; mt < 2; mt++)
#pragma unroll
                for (int nt = 0; nt < 4; nt++)
#pragma unroll
                    for (int q = 0; q < 4; q++) prev[mt][nt][q] = acc[mt][nt][q];
            Ip = I; Jp = J; dtp = (I == J);
            I = I1; J = J1; ap = apn;
        }

        // final epilogue for last tile
        {
            float rlo[2] = {0.f, 0.f}, rhi[2] = {0.f, 0.f};
            float cp0[4] = {0.f, 0.f, 0.f, 0.f}, cp1[4] = {0.f, 0.f, 0.f, 0.f};
#pragma unroll
            for (int ks = 0; ks < 8; ks++) {
                int mt = ks & 1, nt = ks >> 1;
                int lr = lrl0 + mt * 16;
                int lc = lcb0 + nt * 8;
                float v0 = (dtp && lc == lr)         ? EXP_DIAG : ex2f(prev[mt][nt][0] * EXP_SCALE);
                float v1 = (dtp && lc + 1 == lr)     ? EXP_DIAG : ex2f(prev[mt][nt][1] * EXP_SCALE);
                float v2 = (dtp && lc == lr + 8)     ? EXP_DIAG : ex2f(prev[mt][nt][2] * EXP_SCALE);
                float v3 = (dtp && lc + 1 == lr + 8) ? EXP_DIAG : ex2f(prev[mt][nt][3] * EXP_SCALE);
                rlo[mt] += v0 + v1;
                rhi[mt] += v2 + v3;
                cp0[nt] += v0 + v2;
                cp1[nt] += v1 + v3;
            }
            float* red_row = (float*)(smem + RED_OFF + ((cnt - 1) & 1) * RED_PAR);
            float* red_col = red_row + 512;
#pragma unroll
            for (int mt = 0; mt < 2; mt++) {
                rlo[mt] += __shfl_xor_sync(0xFFFFFFFF, rlo[mt], 1);
                rlo[mt] += __shfl_xor_sync(0xFFFFFFFF, rlo[mt], 2);
                rhi[mt] += __shfl_xor_sync(0xFFFFFFFF, rhi[mt], 1);
                rhi[mt] += __shfl_xor_sync(0xFFFFFFFF, rhi[mt], 2);
            }
#pragma unroll
            for (int nt = 0; nt < 4; nt++) {
                cp0[nt] += __shfl_xor_sync(0xFFFFFFFF, cp0[nt], 4);
                cp0[nt] += __shfl_xor_sync(0xFFFFFFFF, cp0[nt], 8);
                cp0[nt] += __shfl_xor_sync(0xFFFFFFFF, cp0[nt], 16);
                cp1[nt] += __shfl_xor_sync(0xFFFFFFFF, cp1[nt], 4);
                cp1[nt] += __shfl_xor_sync(0xFFFFFFFF, cp1[nt], 8);
                cp1[nt] += __shfl_xor_sync(0xFFFFFFFF, cp1[nt], 16);
            }
            if ((lane & 3) == 0) {
#pragma unroll
                for (int mt = 0; mt < 2; mt++) {
                    int r = wy * 32 + mt * 16 + (lane >> 2);
                    red_row[r * 4 + wx] = rlo[mt];
                    red_row[(r + 8) * 4 + wx] = rhi[mt];
                }
            }
            if (lane < 4) {
#pragma unroll
                for (int nt = 0; nt < 4; nt++) {
                    int c = wx * 32 + nt * 8 + lane * 2;
                    red_col[c * 4 + wy] = cp0[nt];
                    red_col[(c + 1) * 4 + wy] = cp1[nt];
                }
            }
            __syncthreads();
            if (tid < 128) {
                float rz = (red_row[tid * 4] + red_row[tid * 4 + 1]) +
                           (red_row[tid * 4 + 2] + red_row[tid * 4 + 3]);
                g_Zp[(size_t)(Ip * 128 + tid) * NT_ROW + Jp] = rz;
                if (!dtp) {
                    float cz = (red_col[tid * 4] + red_col[tid * 4 + 1]) +
                               (red_col[tid * 4 + 2] + red_col[tid * 4 + 3]);
                    g_Zp[(size_t)(Jp * 128 + tid) * NT_ROW + Ip] = cz;
                }
            }
        }
    }
    grid_barrier(1);

    // ================= phase 2: class-sum finalize =================
    if (bid < 4) {
        int item = bid * 512 + tid;          // 2048 items: c = item>>8, d = item&255
        int c = item >> 8, d = item & 255;
        float s = 0.f;
        for (int b = 0; b < NCHUNK; b++) s += g_clsum_part[(b * CLS + c) * DIM + d];
        g_clsum[c * DIM + d] = s;
        if (d == 0) {
            float cn = 0.f;
            for (int b = 0; b < NCHUNK; b++) cn += g_clcnt_part[b * CLS + c];
            g_clcnt[c] = cn;
        }
    }
    grid_barrier(2);

    // ================= phase 3: contrastive per-row =================
    {
        float csum = 0.f;
        for (int row = gw; row < N; row += NWARPS) {
            int t = tgt[row];
            float zs = g_Zp[(size_t)row * NT_ROW + lane] + g_Zp[(size_t)row * NT_ROW + lane + 32];
            const float4* e = (const float4*)&g_embn[(size_t)row * DIM];
            const float4* sc = (const float4*)&g_clsum[t * DIM];
            float dot = 0.f;
#pragma unroll
            for (int k = lane; k < DIM / 4; k += 32) {
                float4 a = e[k], b = sc[k];
                dot += a.x * b.x + a.y * b.y + a.z * b.z + a.w * b.w;
            }
#pragma unroll
            for (int off = 16; off > 0; off >>= 1) {
                dot += __shfl_xor_sync(0xFFFFFFFF, dot, off);
                zs += __shfl_xor_sync(0xFFFFFFFF, zs, off);
            }
            if (lane == 0) {
                float logZ = logf(zs + 1e-8f);
                float npos = g_clcnt[t] - 1.0f;
                float msum = (dot - 1.0f) * INV_T;
                csum += (npos * logZ - msum) / fmaxf(npos, 1.0f);
            }
        }
        if (lane == 0) g_con_part[gw] = csum;
    }
    grid_barrier(3);

    // ================= phase 4: final reduction =================
    if (bid == 0) {
        __shared__ float s[512];
        float cs = 0.f;
        for (int i = tid; i < NWARPS; i += 512) cs += g_con_part[i];
        s[tid] = cs;
        __syncthreads();
        for (int off = 256; off > 0; off >>= 1) {
            if (tid < off) s[tid] += s[tid + off];
            __syncthreads();
        }
        __shared__ float con_sum;
        if (tid == 0) con_sum = s[0];
        __syncthreads();

        float ce = (tid < N / 32) ? g_ce_part[tid] : 0.f;
        s[tid] = ce;
        __syncthreads();
        for (int off = 256; off > 0; off >>= 1) {
            if (tid < off) s[tid] += s[tid + off];
            __syncthreads();
        }
        if (tid == 0) {
            float ce_mean = s[0] * (1.0f / N);
            float con_mean = con_sum * (1.0f / N);
            out[0] = ce_mean + ALPHA * con_mean;
            if (out_size > 1) out[1] = ce_mean;
            if (out_size > 2) out[2] = con_mean;
        }
    }
}

// ---------------- launcher ----------------------------------------------------------
extern "C" void kernel_launch(void* const* d_in, const int* in_sizes, int n_in,
                              void* d_out, int out_size) {
    const float* logits = (const float*)d_in[0];
    const float* emb = (const float*)d_in[1];
    const int* tgt = (const int*)d_in[2];
    float* out = (float*)d_out;

    cudaFuncSetAttribute(k_all, cudaFuncAttributeMaxDynamicSharedMemorySize, SMEM_TOTAL);
    k_all<<<GRID, 512, SMEM_TOTAL>>>(logits, emb, tgt, out, out_size);
}

// round 11
// speedup vs baseline: 1.0378x; 1.0378x over previous
#include <cuda_runtime.h>
#include <math.h>
#include <stdint.h>

#define N 8192
#define CLS 8
#define DIM 256
#define INV_T 14.285714285714286f
#define EXP_SCALE 20.60992915555662f   /* (1/0.07) * log2(e) */
#define ALPHA 0.3f
#define LSM 0.1f
#define NT_ROW 64
#define NCHUNK 128
#define GRID 148
#define NWARPS (GRID * 16)

// ---------------- scratch ------------------------------------------------------------
__device__ float g_embn[N * DIM];
__device__ uint16_t g_embq[N * DIM / 2];
__device__ float g_clsum_part[NCHUNK * CLS * DIM];
__device__ float g_clcnt_part[NCHUNK * CLS];
__device__ float g_clsum[CLS * DIM];
__device__ float g_clcnt[CLS];
__device__ float g_Zp[N * NT_ROW];
__device__ float g_con_part[NWARPS];
__device__ float g_ce_part[16 * 16];
__device__ unsigned g_bar_cnt[8];
__device__ unsigned g_bar_gen[8];

// ---------------- helpers ------------------------------------------------------------
__device__ __forceinline__ uint32_t smem_u32(const void* p) {
    uint32_t a;
    asm("{ .reg .u64 t; cvta.to.shared.u64 t, %1; cvt.u32.u64 %0, t; }" : "=r"(a) : "l"(p));
    return a;
}
__device__ __forceinline__ float ex2f(float x) {
    float y; asm("ex2.approx.f32 %0, %1;" : "=f"(y) : "f"(x)); return y;
}
__device__ __forceinline__ void cp16(uint32_t dst, const void* src) {
    asm volatile("cp.async.cg.shared.global [%0], [%1], 16;" :: "r"(dst), "l"(src));
}
#define CP_COMMIT() asm volatile("cp.async.commit_group;" ::: "memory")
#define CP_WAIT0()  asm volatile("cp.async.wait_group 0;" ::: "memory")

__device__ __forceinline__ void ldsm4(uint32_t& r0, uint32_t& r1, uint32_t& r2, uint32_t& r3,
                                      uint32_t addr) {
    asm volatile("ldmatrix.sync.aligned.m8n8.x4.shared.b16 {%0,%1,%2,%3}, [%4];"
                 : "=r"(r0), "=r"(r1), "=r"(r2), "=r"(r3) : "r"(addr));
}
__device__ __forceinline__ void mma_fp8(float* c, uint32_t a0, uint32_t a1, uint32_t a2,
                                        uint32_t a3, uint32_t b0, uint32_t b1) {
    asm volatile("mma.sync.aligned.m16n8k32.row.col.f32.e4m3.e4m3.f32 "
                 "{%0,%1,%2,%3}, {%4,%5,%6,%7}, {%8,%9}, {%0,%1,%2,%3};"
                 : "+f"(c[0]), "+f"(c[1]), "+f"(c[2]), "+f"(c[3])
                 : "r"(a0), "r"(a1), "r"(a2), "r"(a3), "r"(b0), "r"(b1));
}
__device__ __forceinline__ uint16_t f2e4m3x2(float hi, float lo) {
    uint16_t r;
    asm("cvt.rn.satfinite.e4m3x2.f32 %0, %1, %2;" : "=h"(r) : "f"(hi), "f"(lo));
    return r;
}

// device-wide barrier, monotonic generation (graph-replay safe; proven R10)
__device__ __forceinline__ void grid_barrier(int k) {
    __syncthreads();
    if (threadIdx.x == 0) {
        __threadfence();
        unsigned gen = g_bar_gen[k];
        unsigned t = atomicAdd(&g_bar_cnt[k], 1u);
        if (t == GRID - 1) {
            g_bar_cnt[k] = 0;
            __threadfence();
            atomicAdd(&g_bar_gen[k], 1u);
        } else {
            while (((volatile unsigned*)g_bar_gen)[k] == gen) __nanosleep(64);
            __threadfence();
        }
    }
    __syncthreads();
}

// ---------------- 1) normalize + fp8 convert (warp per row) --------------------------
__global__ void k_norm(const float* __restrict__ emb) {
    int w = threadIdx.x >> 5, lane = threadIdx.x & 31;
    int row = blockIdx.x * 8 + w;
    const float4* src = (const float4*)(emb + (size_t)row * DIM);
    float4 v0 = src[lane * 2], v1 = src[lane * 2 + 1];
    float ss = v0.x * v0.x + v0.y * v0.y + v0.z * v0.z + v0.w * v0.w +
               v1.x * v1.x + v1.y * v1.y + v1.z * v1.z + v1.w * v1.w;
#pragma unroll
    for (int off = 16; off > 0; off >>= 1) ss += __shfl_xor_sync(0xFFFFFFFF, ss, off);
    float inv = 1.0f / fmaxf(sqrtf(ss), 1e-12f);
    v0.x *= inv; v0.y *= inv; v0.z *= inv; v0.w *= inv;
    v1.x *= inv; v1.y *= inv; v1.z *= inv; v1.w *= inv;
    float4* dst = (float4*)(g_embn + (size_t)row * DIM);
    dst[lane * 2] = v0;
    dst[lane * 2 + 1] = v1;
    uint32_t u0 = (uint32_t)f2e4m3x2(v0.y, v0.x) | ((uint32_t)f2e4m3x2(v0.w, v0.z) << 16);
    uint32_t u1 = (uint32_t)f2e4m3x2(v1.y, v1.x) | ((uint32_t)f2e4m3x2(v1.w, v1.z) << 16);
    *(uint2*)(g_embq + (size_t)row * 128 + lane * 4) = make_uint2(u0, u1);
}

// ---------------- 2) HOT: symmetric Z + folded side jobs (identical to R9) -----------
#define SAB 272
#define A_BYTES (128 * SAB)
#define AS(p) ((p) * A_BYTES)
#define BS(b) ((2 + (b)) * A_BYTES)
#define RED_OFF (4 * A_BYTES)
#define RED_PAR 4096
#define SMEM_TOTAL (RED_OFF + 2 * RED_PAR)

__device__ __forceinline__ void load_tile_async(uint32_t sbase, int grow0, int tid) {
    const char* src = (const char*)g_embq + (size_t)grow0 * 256;
#pragma unroll
    for (int i = 0; i < 4; i++) {
        int idx = tid + i * 512;
        int row = idx >> 4, cb = idx & 15;
        cp16(sbase + row * SAB + cb * 16, src + (size_t)row * 256 + cb * 16);
    }
}

__global__ void __launch_bounds__(512, 1) k_sim_sym(const float* __restrict__ logits,
                                                   const int* __restrict__ tgt) {
    extern __shared__ char smem[];
    uint32_t sb = smem_u32(smem);
    int tid = threadIdx.x;
    int lane = tid & 31;
    int wid = tid >> 5;
    int wx = wid & 3;
    int wy = wid >> 2;
    int bid = blockIdx.x;

    int base = bid * 14 + (bid < 8 ? bid : 8);
    int cnt = 14 + (bid < 8 ? 1 : 0);

    int idx = base, I = 0;
    while (idx >= NT_ROW - I) { idx -= NT_ROW - I; I++; }
    int J = I + idx;

    int ap = 0;
    load_tile_async(sb + AS(0), I * 128, tid);
    if (J != I) load_tile_async(sb + BS(0), J * 128, tid);
    CP_COMMIT();

    if (bid >= 8 && bid < 72) {
        int half = tid >> 8;
        int d = tid & 255;
        int chunk = (bid - 8) * 2 + half;
        int i0 = chunk * 64;
        float a[CLS];
#pragma unroll
        for (int c = 0; c < CLS; c++) a[c] = 0.f;
        for (int k = 0; k < 64; k++) {
            int tg = tgt[i0 + k];
            float v = g_embn[(size_t)(i0 + k) * DIM + d];
#pragma unroll
            for (int c = 0; c < CLS; c++) a[c] += (tg == c) ? v : 0.f;
        }
#pragma unroll
        for (int c = 0; c < CLS; c++) g_clsum_part[(chunk * CLS + c) * DIM + d] = a[c];
        if (d == 0) {
            int cc[CLS];
#pragma unroll
            for (int c = 0; c < CLS; c++) cc[c] = 0;
            for (int k = 0; k < 64; k++) {
                int tg = tgt[i0 + k];
#pragma unroll
                for (int c = 0; c < CLS; c++) cc[c] += (tg == c);
            }
#pragma unroll
            for (int c = 0; c < CLS; c++) g_clcnt_part[chunk * CLS + c] = (float)cc[c];
        }
    } else if (bid >= 72 && bid < 88) {
        int chunk = bid - 72;
        int i = chunk * 512 + tid;
        const float4* p = (const float4*)(logits + (size_t)i * CLS);
        float4 u = p[0], w = p[1];
        float x[CLS] = {u.x, u.y, u.z, u.w, w.x, w.y, w.z, w.w};
        float m = x[0];
#pragma unroll
        for (int j = 1; j < CLS; j++) m = fmaxf(m, x[j]);
        float se = 0.f;
#pragma unroll
        for (int j = 0; j < CLS; j++) se += expf(x[j] - m);
        float lse = m + logf(se);
        int tg = tgt[i];
        float nll = lse - x[tg];
        float sx = 0.f;
#pragma unroll
        for (int j = 0; j < CLS; j++) sx += x[j];
        float smooth = lse - sx * (1.0f / CLS);
        float ce = (1.0f - LSM) * nll + LSM * smooth;
        float pt = expf(-ce);
        float omp = 1.0f - pt;
        float focal = omp * omp * ce;
#pragma unroll
        for (int off = 16; off > 0; off >>= 1)
            focal += __shfl_xor_sync(0xFFFFFFFF, focal, off);
        if (lane == 0) g_ce_part[chunk * 16 + wid] = focal;
    }

    CP_WAIT0();
    __syncthreads();

    uint32_t a_lane = (wy * 32 + (lane & 15)) * SAB + ((lane >> 4) << 4);
    uint32_t b_lane = ((lane & 7) + ((lane >> 4) << 3)) * SAB + (((lane >> 3) & 1) << 4) +
                      (wx * 32) * SAB;

    const float EXP_DIAG = expf(INV_T);
    int lrl0 = wy * 32 + (lane >> 2);
    int lcb0 = wx * 32 + (lane & 3) * 2;

    float prev[2][4][4];
    int Ip = 0, Jp = 0;
    bool dtp = false;

    for (int t = 0; t < cnt; t++) {
        int I1 = I, J1 = J + 1;
        if (J1 == NT_ROW) { I1 = I + 1; J1 = I1; }
        bool havenext = (t + 1 < cnt);
        int apn = ap;
        if (havenext) {
            if (I1 != I) {
                apn = ap ^ 1;
                load_tile_async(sb + AS(apn), I1 * 128, tid);
            }
            if (J1 != I1) {
                load_tile_async(sb + BS((t + 1) & 1), J1 * 128, tid);
            }
            CP_COMMIT();
        }

        bool dt = (I == J);
        uint32_t a_addr = sb + AS(ap) + a_lane;
        uint32_t bbuf = (dt ? (sb + AS(ap)) : (sb + BS(t & 1))) + b_lane;

        float acc[2][4][4];
#pragma unroll
        for (int mt = 0; mt < 2; mt++)
#pragma unroll
            for (int nt = 0; nt < 4; nt++)
#pragma unroll
                for (int q = 0; q < 4; q++) acc[mt][nt][q] = 0.f;

        float rlo[2] = {0.f, 0.f}, rhi[2] = {0.f, 0.f};
        float cp0[4] = {0.f, 0.f, 0.f, 0.f}, cp1[4] = {0.f, 0.f, 0.f, 0.f};

#pragma unroll
        for (int ks = 0; ks < 8; ks++) {
            uint32_t koff = ks * 32;
            uint32_t a0[4], a1[4];
            ldsm4(a0[0], a0[1], a0[2], a0[3], a_addr + koff);
            ldsm4(a1[0], a1[1], a1[2], a1[3], a_addr + 16 * SAB + koff);
            uint32_t bfr[2][4];
#pragma unroll
            for (int p = 0; p < 2; p++)
                ldsm4(bfr[p][0], bfr[p][1], bfr[p][2], bfr[p][3],
                      bbuf + (p * 16) * SAB + koff);
#pragma unroll
            for (int nt = 0; nt < 4; nt++) {
                uint32_t bb0 = bfr[nt >> 1][(nt & 1) * 2];
                uint32_t bb1 = bfr[nt >> 1][(nt & 1) * 2 + 1];
                mma_fp8(acc[0][nt], a0[0], a0[1], a0[2], a0[3], bb0, bb1);
                mma_fp8(acc[1][nt], a1[0], a1[1], a1[2], a1[3], bb0, bb1);
            }
            if (t > 0) {
                int mt = ks & 1, nt = ks >> 1;
                int lr = lrl0 + mt * 16;
                int lc = lcb0 + nt * 8;
                float v0 = (dtp && lc == lr)         ? EXP_DIAG : ex2f(prev[mt][nt][0] * EXP_SCALE);
                float v1 = (dtp && lc + 1 == lr)     ? EXP_DIAG : ex2f(prev[mt][nt][1] * EXP_SCALE);
                float v2 = (dtp && lc == lr + 8)     ? EXP_DIAG : ex2f(prev[mt][nt][2] * EXP_SCALE);
                float v3 = (dtp && lc + 1 == lr + 8) ? EXP_DIAG : ex2f(prev[mt][nt][3] * EXP_SCALE);
                rlo[mt] += v0 + v1;
                rhi[mt] += v2 + v3;
                cp0[nt] += v0 + v2;
                cp1[nt] += v1 + v3;
            }
        }

        if (t > 0) {
            float* red_row = (float*)(smem + RED_OFF + ((t - 1) & 1) * RED_PAR);
            float* red_col = red_row + 512;
#pragma unroll
            for (int mt = 0; mt < 2; mt++) {
                rlo[mt] += __shfl_xor_sync(0xFFFFFFFF, rlo[mt], 1);
                rlo[mt] += __shfl_xor_sync(0xFFFFFFFF, rlo[mt], 2);
                rhi[mt] += __shfl_xor_sync(0xFFFFFFFF, rhi[mt], 1);
                rhi[mt] += __shfl_xor_sync(0xFFFFFFFF, rhi[mt], 2);
            }
#pragma unroll
            for (int nt = 0; nt < 4; nt++) {
                cp0[nt] += __shfl_xor_sync(0xFFFFFFFF, cp0[nt], 4);
                cp0[nt] += __shfl_xor_sync(0xFFFFFFFF, cp0[nt], 8);
                cp0[nt] += __shfl_xor_sync(0xFFFFFFFF, cp0[nt], 16);
                cp1[nt] += __shfl_xor_sync(0xFFFFFFFF, cp1[nt], 4);
                cp1[nt] += __shfl_xor_sync(0xFFFFFFFF, cp1[nt], 8);
                cp1[nt] += __shfl_xor_sync(0xFFFFFFFF, cp1[nt], 16);
            }
            if ((lane & 3) == 0) {
#pragma unroll
                for (int mt = 0; mt < 2; mt++) {
                    int r = wy * 32 + mt * 16 + (lane >> 2);
                    red_row[r * 4 + wx] = rlo[mt];
                    red_row[(r + 8) * 4 + wx] = rhi[mt];
                }
            }
            if (lane < 4) {
#pragma unroll
                for (int nt = 0; nt < 4; nt++) {
                    int c = wx * 32 + nt * 8 + lane * 2;
                    red_col[c * 4 + wy] = cp0[nt];
                    red_col[(c + 1) * 4 + wy] = cp1[nt];
                }
            }
        }
        if (havenext) CP_WAIT0();
        __syncthreads();
        if (t > 0 && tid < 128) {
            float* red_row = (float*)(smem + RED_OFF + ((t - 1) & 1) * RED_PAR);
            float* red_col = red_row + 512;
            float rz = (red_row[tid * 4] + red_row[tid * 4 + 1]) +
                       (red_row[tid * 4 + 2] + red_row[tid * 4 + 3]);
            g_Zp[(size_t)(Ip * 128 + tid) * NT_ROW + Jp] = rz;
            if (!dtp) {
                float cz = (red_col[tid * 4] + red_col[tid * 4 + 1]) +
                           (red_col[tid * 4 + 2] + red_col[tid * 4 + 3]);
                g_Zp[(size_t)(Jp * 128 + tid) * NT_ROW + Ip] = cz;
            }
        }

#pragma unroll
        for (int mt = 0; mt < 2; mt++)
#pragma unroll
            for (int nt = 0; nt < 4; nt++)
#pragma unroll
                for (int q = 0; q < 4; q++) prev[mt][nt][q] = acc[mt][nt][q];
        Ip = I; Jp = J; dtp = (I == J);
        I = I1; J = J1; ap = apn;
    }

    // final epilogue for last tile
    {
        float rlo[2] = {0.f, 0.f}, rhi[2] = {0.f, 0.f};
        float cp0[4] = {0.f, 0.f, 0.f, 0.f}, cp1[4] = {0.f, 0.f, 0.f, 0.f};
#pragma unroll
        for (int ks = 0; ks < 8; ks++) {
            int mt = ks & 1, nt = ks >> 1;
            int lr = lrl0 + mt * 16;
            int lc = lcb0 + nt * 8;
            float v0 = (dtp && lc == lr)         ? EXP_DIAG : ex2f(prev[mt][nt][0] * EXP_SCALE);
            float v1 = (dtp && lc + 1 == lr)     ? EXP_DIAG : ex2f(prev[mt][nt][1] * EXP_SCALE);
            float v2 = (dtp && lc == lr + 8)     ? EXP_DIAG : ex2f(prev[mt][nt][2] * EXP_SCALE);
            float v3 = (dtp && lc + 1 == lr + 8) ? EXP_DIAG : ex2f(prev[mt][nt][3] * EXP_SCALE);
            rlo[mt] += v0 + v1;
            rhi[mt] += v2 + v3;
            cp0[nt] += v0 + v2;
            cp1[nt] += v1 + v3;
        }
        float* red_row = (float*)(smem + RED_OFF + ((cnt - 1) & 1) * RED_PAR);
        float* red_col = red_row + 512;
#pragma unroll
        for (int mt = 0; mt < 2; mt++) {
            rlo[mt] += __shfl_xor_sync(0xFFFFFFFF, rlo[mt], 1);
            rlo[mt] += __shfl_xor_sync(0xFFFFFFFF, rlo[mt], 2);
            rhi[mt] += __shfl_xor_sync(0xFFFFFFFF, rhi[mt], 1);
            rhi[mt] += __shfl_xor_sync(0xFFFFFFFF, rhi[mt], 2);
        }
#pragma unroll
        for (int nt = 0; nt < 4; nt++) {
            cp0[nt] += __shfl_xor_sync(0xFFFFFFFF, cp0[nt], 4);
            cp0[nt] += __shfl_xor_sync(0xFFFFFFFF, cp0[nt], 8);
            cp0[nt] += __shfl_xor_sync(0xFFFFFFFF, cp0[nt], 16);
            cp1[nt] += __shfl_xor_sync(0xFFFFFFFF, cp1[nt], 4);
            cp1[nt] += __shfl_xor_sync(0xFFFFFFFF, cp1[nt], 8);
            cp1[nt] += __shfl_xor_sync(0xFFFFFFFF, cp1[nt], 16);
        }
        if ((lane & 3) == 0) {
#pragma unroll
            for (int mt = 0; mt < 2; mt++) {
                int r = wy * 32 + mt * 16 + (lane >> 2);
                red_row[r * 4 + wx] = rlo[mt];
                red_row[(r + 8) * 4 + wx] = rhi[mt];
            }
        }
        if (lane < 4) {
#pragma unroll
            for (int nt = 0; nt < 4; nt++) {
                int c = wx * 32 + nt * 8 + lane * 2;
                red_col[c * 4 + wy] = cp0[nt];
                red_col[(c + 1) * 4 + wy] = cp1[nt];
            }
        }
        __syncthreads();
        if (tid < 128) {
            float rz = (red_row[tid * 4] + red_row[tid * 4 + 1]) +
                       (red_row[tid * 4 + 2] + red_row[tid * 4 + 3]);
            g_Zp[(size_t)(Ip * 128 + tid) * NT_ROW + Jp] = rz;
            if (!dtp) {
                float cz = (red_col[tid * 4] + red_col[tid * 4 + 1]) +
                           (red_col[tid * 4 + 2] + red_col[tid * 4 + 3]);
                g_Zp[(size_t)(Jp * 128 + tid) * NT_ROW + Ip] = cz;
            }
        }
    }
}

// ---------------- 3) fused tail: clsum-finalize + contrastive + final ----------------
__global__ void __launch_bounds__(512) k_tail(const int* __restrict__ tgt,
                                              float* __restrict__ out, int out_size) {
    int tid = threadIdx.x;
    int lane = tid & 31;
    int wid = tid >> 5;
    int bid = blockIdx.x;
    int gw = bid * 16 + wid;

    // phase A: class-sum finalize (first 2048 global threads)
    if (bid < 4) {
        int item = bid * 512 + tid;
        int c = item >> 8, d = item & 255;
        float s = 0.f;
        for (int b = 0; b < NCHUNK; b++) s += g_clsum_part[(b * CLS + c) * DIM + d];
        g_clsum[c * DIM + d] = s;
        if (d == 0) {
            float cn = 0.f;
            for (int b = 0; b < NCHUNK; b++) cn += g_clcnt_part[b * CLS + c];
            g_clcnt[c] = cn;
        }
    }
    grid_barrier(0);

    // phase B: per-row contrastive, 2368 warps
    {
        float csum = 0.f;
        for (int row = gw; row < N; row += NWARPS) {
            int t = tgt[row];
            float zs = g_Zp[(size_t)row * NT_ROW + lane] + g_Zp[(size_t)row * NT_ROW + lane + 32];
            const float4* e = (const float4*)&g_embn[(size_t)row * DIM];
            const float4* sc = (const float4*)&g_clsum[t * DIM];
            float dot = 0.f;
#pragma unroll
            for (int k = lane; k < DIM / 4; k += 32) {
                float4 a = e[k], b = sc[k];
                dot += a.x * b.x + a.y * b.y + a.z * b.z + a.w * b.w;
            }
#pragma unroll
            for (int off = 16; off > 0; off >>= 1) {
                dot += __shfl_xor_sync(0xFFFFFFFF, dot, off);
                zs += __shfl_xor_sync(0xFFFFFFFF, zs, off);
            }
            if (lane == 0) {
                float logZ = logf(zs + 1e-8f);
                float npos = g_clcnt[t] - 1.0f;
                float msum = (dot - 1.0f) * INV_T;
                csum += (npos * logZ - msum) / fmaxf(npos, 1.0f);
            }
        }
        if (lane == 0) g_con_part[gw] = csum;
    }
    grid_barrier(1);

    // phase C: final reduction on CTA 0
    if (bid == 0) {
        __shared__ float s[512];
        float cs = 0.f;
        for (int i = tid; i < NWARPS; i += 512) cs += g_con_part[i];
        s[tid] = cs;
        __syncthreads();
        for (int off = 256; off > 0; off >>= 1) {
            if (tid < off) s[tid] += s[tid + off];
            __syncthreads();
        }
        __shared__ float con_sum;
        if (tid == 0) con_sum = s[0];
        __syncthreads();

        s[tid] = (tid < 256) ? g_ce_part[tid] : 0.f;
        __syncthreads();
        for (int off = 256; off > 0; off >>= 1) {
            if (tid < off) s[tid] += s[tid + off];
            __syncthreads();
        }
        if (tid == 0) {
            float ce_mean = s[0] * (1.0f / N);
            float con_mean = con_sum * (1.0f / N);
            out[0] = ce_mean + ALPHA * con_mean;
            if (out_size > 1) out[1] = ce_mean;
            if (out_size > 2) out[2] = con_mean;
        }
    }
}

// ---------------- launcher ----------------------------------------------------------
extern "C" void kernel_launch(void* const* d_in, const int* in_sizes, int n_in,
                              void* d_out, int out_size) {
    const float* logits = (const float*)d_in[0];
    const float* emb = (const float*)d_in[1];
    const int* tgt = (const int*)d_in[2];
    float* out = (float*)d_out;

    cudaFuncSetAttribute(k_sim_sym, cudaFuncAttributeMaxDynamicSharedMemorySize, SMEM_TOTAL);

    k_norm<<<N / 8, 256>>>(emb);
    k_sim_sym<<<GRID, 512, SMEM_TOTAL>>>(logits, tgt);
    k_tail<<<GRID, 512>>>(tgt, out, out_size);
}

// round 12
// speedup vs baseline: 1.0622x; 1.0234x over previous
#include <cuda_runtime.h>
#include <math.h>
#include <stdint.h>

#define N 8192
#define CLS 8
#define DIM 256
#define INV_T 14.285714285714286f
#define EXP_SCALE 20.60992915555662f   /* (1/0.07) * log2(e) */
#define ALPHA 0.3f
#define LSM 0.1f
#define NT_ROW 64
#define NCHUNK 128

// ---------------- scratch ------------------------------------------------------------
__device__ float g_embn[N * DIM];
__device__ uint16_t g_embq[N * DIM / 2];
__device__ float g_clsum_part[NCHUNK * CLS * DIM];
__device__ float g_clcnt_part[NCHUNK * CLS];
__device__ float g_clsum[CLS * DIM];
__device__ float g_clcnt[CLS];
__device__ float g_Zp[N * NT_ROW];
__device__ float g_con[N];
__device__ float g_ce_part[16 * 16];

// ---------------- helpers ------------------------------------------------------------
__device__ __forceinline__ uint32_t smem_u32(const void* p) {
    uint32_t a;
    asm("{ .reg .u64 t; cvta.to.shared.u64 t, %1; cvt.u32.u64 %0, t; }" : "=r"(a) : "l"(p));
    return a;
}
__device__ __forceinline__ float ex2f(float x) {
    float y; asm("ex2.approx.f32 %0, %1;" : "=f"(y) : "f"(x)); return y;
}
__device__ __forceinline__ void cp16(uint32_t dst, const void* src) {
    asm volatile("cp.async.cg.shared.global [%0], [%1], 16;" :: "r"(dst), "l"(src));
}
#define CP_COMMIT() asm volatile("cp.async.commit_group;" ::: "memory")
#define CP_WAIT0()  asm volatile("cp.async.wait_group 0;" ::: "memory")

__device__ __forceinline__ void ldsm4(uint32_t& r0, uint32_t& r1, uint32_t& r2, uint32_t& r3,
                                      uint32_t addr) {
    asm volatile("ldmatrix.sync.aligned.m8n8.x4.shared.b16 {%0,%1,%2,%3}, [%4];"
                 : "=r"(r0), "=r"(r1), "=r"(r2), "=r"(r3) : "r"(addr));
}
__device__ __forceinline__ void mma_fp8(float* c, uint32_t a0, uint32_t a1, uint32_t a2,
                                        uint32_t a3, uint32_t b0, uint32_t b1) {
    asm volatile("mma.sync.aligned.m16n8k32.row.col.f32.e4m3.e4m3.f32 "
                 "{%0,%1,%2,%3}, {%4,%5,%6,%7}, {%8,%9}, {%0,%1,%2,%3};"
                 : "+f"(c[0]), "+f"(c[1]), "+f"(c[2]), "+f"(c[3])
                 : "r"(a0), "r"(a1), "r"(a2), "r"(a3), "r"(b0), "r"(b1));
}
__device__ __forceinline__ uint16_t f2e4m3x2(float hi, float lo) {
    uint16_t r;
    asm("cvt.rn.satfinite.e4m3x2.f32 %0, %1, %2;" : "=h"(r) : "f"(hi), "f"(lo));
    return r;
}

// ---------------- 1) normalize + fp8 convert: 4 rows per warp (MLP=8) ----------------
__global__ void k_norm(const float* __restrict__ emb) {
    int w = threadIdx.x >> 5, lane = threadIdx.x & 31;
    int row0 = blockIdx.x * 32 + w * 4;

    float4 v[4][2];
    // issue all 8 loads before any dependent work
#pragma unroll
    for (int r = 0; r < 4; r++) {
        const float4* src = (const float4*)(emb + (size_t)(row0 + r) * DIM);
        v[r][0] = src[lane * 2];
        v[r][1] = src[lane * 2 + 1];
    }
    float ss[4];
#pragma unroll
    for (int r = 0; r < 4; r++) {
        float4 a = v[r][0], b = v[r][1];
        ss[r] = a.x * a.x + a.y * a.y + a.z * a.z + a.w * a.w +
                b.x * b.x + b.y * b.y + b.z * b.z + b.w * b.w;
    }
    // 4 independent shfl chains — pipeline in the issue stream
#pragma unroll
    for (int off = 16; off > 0; off >>= 1) {
#pragma unroll
        for (int r = 0; r < 4; r++) ss[r] += __shfl_xor_sync(0xFFFFFFFF, ss[r], off);
    }
#pragma unroll
    for (int r = 0; r < 4; r++) {
        float inv = 1.0f / fmaxf(sqrtf(ss[r]), 1e-12f);
        float4 a = v[r][0], b = v[r][1];
        a.x *= inv; a.y *= inv; a.z *= inv; a.w *= inv;
        b.x *= inv; b.y *= inv; b.z *= inv; b.w *= inv;
        float4* dst = (float4*)(g_embn + (size_t)(row0 + r) * DIM);
        dst[lane * 2] = a;
        dst[lane * 2 + 1] = b;
        uint32_t u0 = (uint32_t)f2e4m3x2(a.y, a.x) | ((uint32_t)f2e4m3x2(a.w, a.z) << 16);
        uint32_t u1 = (uint32_t)f2e4m3x2(b.y, b.x) | ((uint32_t)f2e4m3x2(b.w, b.z) << 16);
        *(uint2*)(g_embq + (size_t)(row0 + r) * 128 + lane * 4) = make_uint2(u0, u1);
    }
}

// ---------------- 2) HOT: symmetric Z + folded side jobs (identical to R9) -----------
#define SAB 272
#define A_BYTES (128 * SAB)
#define AS(p) ((p) * A_BYTES)
#define BS(b) ((2 + (b)) * A_BYTES)
#define RED_OFF (4 * A_BYTES)
#define RED_PAR 4096
#define SMEM_TOTAL (RED_OFF + 2 * RED_PAR)

__device__ __forceinline__ void load_tile_async(uint32_t sbase, int grow0, int tid) {
    const char* src = (const char*)g_embq + (size_t)grow0 * 256;
#pragma unroll
    for (int i = 0; i < 4; i++) {
        int idx = tid + i * 512;
        int row = idx >> 4, cb = idx & 15;
        cp16(sbase + row * SAB + cb * 16, src + (size_t)row * 256 + cb * 16);
    }
}

__global__ void __launch_bounds__(512, 1) k_sim_sym(const float* __restrict__ logits,
                                                   const int* __restrict__ tgt) {
    extern __shared__ char smem[];
    uint32_t sb = smem_u32(smem);
    int tid = threadIdx.x;
    int lane = tid & 31;
    int wid = tid >> 5;
    int wx = wid & 3;
    int wy = wid >> 2;
    int bid = blockIdx.x;

    int base = bid * 14 + (bid < 8 ? bid : 8);
    int cnt = 14 + (bid < 8 ? 1 : 0);

    int idx = base, I = 0;
    while (idx >= NT_ROW - I) { idx -= NT_ROW - I; I++; }
    int J = I + idx;

    int ap = 0;
    load_tile_async(sb + AS(0), I * 128, tid);
    if (J != I) load_tile_async(sb + BS(0), J * 128, tid);
    CP_COMMIT();

    if (bid >= 8 && bid < 72) {
        int half = tid >> 8;
        int d = tid & 255;
        int chunk = (bid - 8) * 2 + half;
        int i0 = chunk * 64;
        float a[CLS];
#pragma unroll
        for (int c = 0; c < CLS; c++) a[c] = 0.f;
        for (int k = 0; k < 64; k++) {
            int tg = tgt[i0 + k];
            float v = g_embn[(size_t)(i0 + k) * DIM + d];
#pragma unroll
            for (int c = 0; c < CLS; c++) a[c] += (tg == c) ? v : 0.f;
        }
#pragma unroll
        for (int c = 0; c < CLS; c++) g_clsum_part[(chunk * CLS + c) * DIM + d] = a[c];
        if (d == 0) {
            int cc[CLS];
#pragma unroll
            for (int c = 0; c < CLS; c++) cc[c] = 0;
            for (int k = 0; k < 64; k++) {
                int tg = tgt[i0 + k];
#pragma unroll
                for (int c = 0; c < CLS; c++) cc[c] += (tg == c);
            }
#pragma unroll
            for (int c = 0; c < CLS; c++) g_clcnt_part[chunk * CLS + c] = (float)cc[c];
        }
    } else if (bid >= 72 && bid < 88) {
        int chunk = bid - 72;
        int i = chunk * 512 + tid;
        const float4* p = (const float4*)(logits + (size_t)i * CLS);
        float4 u = p[0], w = p[1];
        float x[CLS] = {u.x, u.y, u.z, u.w, w.x, w.y, w.z, w.w};
        float m = x[0];
#pragma unroll
        for (int j = 1; j < CLS; j++) m = fmaxf(m, x[j]);
        float se = 0.f;
#pragma unroll
        for (int j = 0; j < CLS; j++) se += expf(x[j] - m);
        float lse = m + logf(se);
        int tg = tgt[i];
        float nll = lse - x[tg];
        float sx = 0.f;
#pragma unroll
        for (int j = 0; j < CLS; j++) sx += x[j];
        float smooth = lse - sx * (1.0f / CLS);
        float ce = (1.0f - LSM) * nll + LSM * smooth;
        float pt = expf(-ce);
        float omp = 1.0f - pt;
        float focal = omp * omp * ce;
#pragma unroll
        for (int off = 16; off > 0; off >>= 1)
            focal += __shfl_xor_sync(0xFFFFFFFF, focal, off);
        if (lane == 0) g_ce_part[chunk * 16 + wid] = focal;
    }

    CP_WAIT0();
    __syncthreads();

    uint32_t a_lane = (wy * 32 + (lane & 15)) * SAB + ((lane >> 4) << 4);
    uint32_t b_lane = ((lane & 7) + ((lane >> 4) << 3)) * SAB + (((lane >> 3) & 1) << 4) +
                      (wx * 32) * SAB;

    const float EXP_DIAG = expf(INV_T);
    int lrl0 = wy * 32 + (lane >> 2);
    int lcb0 = wx * 32 + (lane & 3) * 2;

    float prev[2][4][4];
    int Ip = 0, Jp = 0;
    bool dtp = false;

    for (int t = 0; t < cnt; t++) {
        int I1 = I, J1 = J + 1;
        if (J1 == NT_ROW) { I1 = I + 1; J1 = I1; }
        bool havenext = (t + 1 < cnt);
        int apn = ap;
        if (havenext) {
            if (I1 != I) {
                apn = ap ^ 1;
                load_tile_async(sb + AS(apn), I1 * 128, tid);
            }
            if (J1 != I1) {
                load_tile_async(sb + BS((t + 1) & 1), J1 * 128, tid);
            }
            CP_COMMIT();
        }

        bool dt = (I == J);
        uint32_t a_addr = sb + AS(ap) + a_lane;
        uint32_t bbuf = (dt ? (sb + AS(ap)) : (sb + BS(t & 1))) + b_lane;

        float acc[2][4][4];
#pragma unroll
        for (int mt = 0; mt < 2; mt++)
#pragma unroll
            for (int nt = 0; nt < 4; nt++)
#pragma unroll
                for (int q = 0; q < 4; q++) acc[mt][nt][q] = 0.f;

        float rlo[2] = {0.f, 0.f}, rhi[2] = {0.f, 0.f};
        float cp0[4] = {0.f, 0.f, 0.f, 0.f}, cp1[4] = {0.f, 0.f, 0.f, 0.f};

#pragma unroll
        for (int ks = 0; ks < 8; ks++) {
            uint32_t koff = ks * 32;
            uint32_t a0[4], a1[4];
            ldsm4(a0[0], a0[1], a0[2], a0[3], a_addr + koff);
            ldsm4(a1[0], a1[1], a1[2], a1[3], a_addr + 16 * SAB + koff);
            uint32_t bfr[2][4];
#pragma unroll
            for (int p = 0; p < 2; p++)
                ldsm4(bfr[p][0], bfr[p][1], bfr[p][2], bfr[p][3],
                      bbuf + (p * 16) * SAB + koff);
#pragma unroll
            for (int nt = 0; nt < 4; nt++) {
                uint32_t bb0 = bfr[nt >> 1][(nt & 1) * 2];
                uint32_t bb1 = bfr[nt >> 1][(nt & 1) * 2 + 1];
                mma_fp8(acc[0][nt], a0[0], a0[1], a0[2], a0[3], bb0, bb1);
                mma_fp8(acc[1][nt], a1[0], a1[1], a1[2], a1[3], bb0, bb1);
            }
            if (t > 0) {
                int mt = ks & 1, nt = ks >> 1;
                int lr = lrl0 + mt * 16;
                int lc = lcb0 + nt * 8;
                float v0 = (dtp && lc == lr)         ? EXP_DIAG : ex2f(prev[mt][nt][0] * EXP_SCALE);
                float v1 = (dtp && lc + 1 == lr)     ? EXP_DIAG : ex2f(prev[mt][nt][1] * EXP_SCALE);
                float v2 = (dtp && lc == lr + 8)     ? EXP_DIAG : ex2f(prev[mt][nt][2] * EXP_SCALE);
                float v3 = (dtp && lc + 1 == lr + 8) ? EXP_DIAG : ex2f(prev[mt][nt][3] * EXP_SCALE);
                rlo[mt] += v0 + v1;
                rhi[mt] += v2 + v3;
                cp0[nt] += v0 + v2;
                cp1[nt] += v1 + v3;
            }
        }

        if (t > 0) {
            float* red_row = (float*)(smem + RED_OFF + ((t - 1) & 1) * RED_PAR);
            float* red_col = red_row + 512;
#pragma unroll
            for (int mt = 0; mt < 2; mt++) {
                rlo[mt] += __shfl_xor_sync(0xFFFFFFFF, rlo[mt], 1);
                rlo[mt] += __shfl_xor_sync(0xFFFFFFFF, rlo[mt], 2);
                rhi[mt] += __shfl_xor_sync(0xFFFFFFFF, rhi[mt], 1);
                rhi[mt] += __shfl_xor_sync(0xFFFFFFFF, rhi[mt], 2);
            }
#pragma unroll
            for (int nt = 0; nt < 4; nt++) {
                cp0[nt] += __shfl_xor_sync(0xFFFFFFFF, cp0[nt], 4);
                cp0[nt] += __shfl_xor_sync(0xFFFFFFFF, cp0[nt], 8);
                cp0[nt] += __shfl_xor_sync(0xFFFFFFFF, cp0[nt], 16);
                cp1[nt] += __shfl_xor_sync(0xFFFFFFFF, cp1[nt], 4);
                cp1[nt] += __shfl_xor_sync(0xFFFFFFFF, cp1[nt], 8);
                cp1[nt] += __shfl_xor_sync(0xFFFFFFFF, cp1[nt], 16);
            }
            if ((lane & 3) == 0) {
#pragma unroll
                for (int mt = 0; mt < 2; mt++) {
                    int r = wy * 32 + mt * 16 + (lane >> 2);
                    red_row[r * 4 + wx] = rlo[mt];
                    red_row[(r + 8) * 4 + wx] = rhi[mt];
                }
            }
            if (lane < 4) {
#pragma unroll
                for (int nt = 0; nt < 4; nt++) {
                    int c = wx * 32 + nt * 8 + lane * 2;
                    red_col[c * 4 + wy] = cp0[nt];
                    red_col[(c + 1) * 4 + wy] = cp1[nt];
                }
            }
        }
        if (havenext) CP_WAIT0();
        __syncthreads();
        if (t > 0 && tid < 128) {
            float* red_row = (float*)(smem + RED_OFF + ((t - 1) & 1) * RED_PAR);
            float* red_col = red_row + 512;
            float rz = (red_row[tid * 4] + red_row[tid * 4 + 1]) +
                       (red_row[tid * 4 + 2] + red_row[tid * 4 + 3]);
            g_Zp[(size_t)(Ip * 128 + tid) * NT_ROW + Jp] = rz;
            if (!dtp) {
                float cz = (red_col[tid * 4] + red_col[tid * 4 + 1]) +
                           (red_col[tid * 4 + 2] + red_col[tid * 4 + 3]);
                g_Zp[(size_t)(Jp * 128 + tid) * NT_ROW + Ip] = cz;
            }
        }

#pragma unroll
        for (int mt = 0; mt < 2; mt++)
#pragma unroll
            for (int nt = 0; nt < 4; nt++)
#pragma unroll
                for (int q = 0; q < 4; q++) prev[mt][nt][q] = acc[mt][nt][q];
        Ip = I; Jp = J; dtp = (I == J);
        I = I1; J = J1; ap = apn;
    }

    // final epilogue for last tile
    {
        float rlo[2] = {0.f, 0.f}, rhi[2] = {0.f, 0.f};
        float cp0[4] = {0.f, 0.f, 0.f, 0.f}, cp1[4] = {0.f, 0.f, 0.f, 0.f};
#pragma unroll
        for (int ks = 0; ks < 8; ks++) {
            int mt = ks & 1, nt = ks >> 1;
            int lr = lrl0 + mt * 16;
            int lc = lcb0 + nt * 8;
            float v0 = (dtp && lc == lr)         ? EXP_DIAG : ex2f(prev[mt][nt][0] * EXP_SCALE);
            float v1 = (dtp && lc + 1 == lr)     ? EXP_DIAG : ex2f(prev[mt][nt][1] * EXP_SCALE);
            float v2 = (dtp && lc == lr + 8)     ? EXP_DIAG : ex2f(prev[mt][nt][2] * EXP_SCALE);
            float v3 = (dtp && lc + 1 == lr + 8) ? EXP_DIAG : ex2f(prev[mt][nt][3] * EXP_SCALE);
            rlo[mt] += v0 + v1;
            rhi[mt] += v2 + v3;
            cp0[nt] += v0 + v2;
            cp1[nt] += v1 + v3;
        }
        float* red_row = (float*)(smem + RED_OFF + ((cnt - 1) & 1) * RED_PAR);
        float* red_col = red_row + 512;
#pragma unroll
        for (int mt = 0; mt < 2; mt++) {
            rlo[mt] += __shfl_xor_sync(0xFFFFFFFF, rlo[mt], 1);
            rlo[mt] += __shfl_xor_sync(0xFFFFFFFF, rlo[mt], 2);
            rhi[mt] += __shfl_xor_sync(0xFFFFFFFF, rhi[mt], 1);
            rhi[mt] += __shfl_xor_sync(0xFFFFFFFF, rhi[mt], 2);
        }
#pragma unroll
        for (int nt = 0; nt < 4; nt++) {
            cp0[nt] += __shfl_xor_sync(0xFFFFFFFF, cp0[nt], 4);
            cp0[nt] += __shfl_xor_sync(0xFFFFFFFF, cp0[nt], 8);
            cp0[nt] += __shfl_xor_sync(0xFFFFFFFF, cp0[nt], 16);
            cp1[nt] += __shfl_xor_sync(0xFFFFFFFF, cp1[nt], 4);
            cp1[nt] += __shfl_xor_sync(0xFFFFFFFF, cp1[nt], 8);
            cp1[nt] += __shfl_xor_sync(0xFFFFFFFF, cp1[nt], 16);
        }
        if ((lane & 3) == 0) {
#pragma unroll
            for (int mt = 0; mt < 2; mt++) {
                int r = wy * 32 + mt * 16 + (lane >> 2);
                red_row[r * 4 + wx] = rlo[mt];
                red_row[(r + 8) * 4 + wx] = rhi[mt];
            }
        }
        if (lane < 4) {
#pragma unroll
            for (int nt = 0; nt < 4; nt++) {
                int c = wx * 32 + nt * 8 + lane * 2;
                red_col[c * 4 + wy] = cp0[nt];
                red_col[(c + 1) * 4 + wy] = cp1[nt];
            }
        }
        __syncthreads();
        if (tid < 128) {
            float rz = (red_row[tid * 4] + red_row[tid * 4 + 1]) +
                       (red_row[tid * 4 + 2] + red_row[tid * 4 + 3]);
            g_Zp[(size_t)(Ip * 128 + tid) * NT_ROW + Jp] = rz;
            if (!dtp) {
                float cz = (red_col[tid * 4] + red_col[tid * 4 + 1]) +
                           (red_col[tid * 4 + 2] + red_col[tid * 4 + 3]);
                g_Zp[(size_t)(Jp * 128 + tid) * NT_ROW + Ip] = cz;
            }
        }
    }
}

// ---------------- 3) class-sum finalize ----------------------------------------------
__global__ void k_clsfinal() {
    int c = blockIdx.x, d = threadIdx.x;
    float s = 0.f;
    for (int b = 0; b < NCHUNK; b++) s += g_clsum_part[(b * CLS + c) * DIM + d];
    g_clsum[c * DIM + d] = s;
    if (d == 0) {
        float cn = 0.f;
        for (int b = 0; b < NCHUNK; b++) cn += g_clcnt_part[b * CLS + c];
        g_clcnt[c] = cn;
    }
}

// ---------------- 4) per-row contrastive loss: 2 rows per warp (MLP up) ---------------
__global__ void k_con(const int* __restrict__ tgt) {
    int w = threadIdx.x >> 5, lane = threadIdx.x & 31;
    int row0 = blockIdx.x * 16 + w * 2;

    int t0 = tgt[row0], t1 = tgt[row0 + 1];
    // issue all independent loads up front
    float zs0 = g_Zp[(size_t)row0 * NT_ROW + lane] + g_Zp[(size_t)row0 * NT_ROW + lane + 32];
    float zs1 = g_Zp[(size_t)(row0 + 1) * NT_ROW + lane] +
                g_Zp[(size_t)(row0 + 1) * NT_ROW + lane + 32];

    const float4* e0 = (const float4*)&g_embn[(size_t)row0 * DIM];
    const float4* e1 = (const float4*)&g_embn[(size_t)(row0 + 1) * DIM];
    const float4* s0 = (const float4*)&g_clsum[t0 * DIM];
    const float4* s1 = (const float4*)&g_clsum[t1 * DIM];

    float dot0 = 0.f, dot1 = 0.f;
#pragma unroll
    for (int k = lane; k < DIM / 4; k += 32) {
        float4 a0 = e0[k], b0 = s0[k];
        float4 a1 = e1[k], b1 = s1[k];
        dot0 += a0.x * b0.x + a0.y * b0.y + a0.z * b0.z + a0.w * b0.w;
        dot1 += a1.x * b1.x + a1.y * b1.y + a1.z * b1.z + a1.w * b1.w;
    }
#pragma unroll
    for (int off = 16; off > 0; off >>= 1) {
        dot0 += __shfl_xor_sync(0xFFFFFFFF, dot0, off);
        dot1 += __shfl_xor_sync(0xFFFFFFFF, dot1, off);
        zs0 += __shfl_xor_sync(0xFFFFFFFF, zs0, off);
        zs1 += __shfl_xor_sync(0xFFFFFFFF, zs1, off);
    }
    if (lane == 0) {
        float logZ0 = logf(zs0 + 1e-8f);
        float np0 = g_clcnt[t0] - 1.0f;
        g_con[row0] = (np0 * logZ0 - (dot0 - 1.0f) * INV_T) / fmaxf(np0, 1.0f);
        float logZ1 = logf(zs1 + 1e-8f);
        float np1 = g_clcnt[t1] - 1.0f;
        g_con[row0 + 1] = (np1 * logZ1 - (dot1 - 1.0f) * INV_T) / fmaxf(np1, 1.0f);
    }
}

// ---------------- 5) final reduction -------------------------------------------------
__global__ void k_final(float* __restrict__ out, int out_size) {
    __shared__ float s[256];
    int t = threadIdx.x;

    float cs = 0.f;
    for (int i = t; i < N; i += 256) cs += g_con[i];
    s[t] = cs;
    __syncthreads();
    for (int off = 128; off > 0; off >>= 1) {
        if (t < off) s[t] += s[t + off];
        __syncthreads();
    }
    __shared__ float con_sum;
    if (t == 0) con_sum = s[0];
    __syncthreads();

    s[t] = g_ce_part[t];
    __syncthreads();
    for (int off = 128; off > 0; off >>= 1) {
        if (t < off) s[t] += s[t + off];
        __syncthreads();
    }
    if (t == 0) {
        float ce_mean = s[0] * (1.0f / N);
        float con_mean = con_sum * (1.0f / N);
        out[0] = ce_mean + ALPHA * con_mean;
        if (out_size > 1) out[1] = ce_mean;
        if (out_size > 2) out[2] = con_mean;
    }
}

// ---------------- launcher ----------------------------------------------------------
extern "C" void kernel_launch(void* const* d_in, const int* in_sizes, int n_in,
                              void* d_out, int out_size) {
    const float* logits = (const float*)d_in[0];
    const float* emb = (const float*)d_in[1];
    const int* tgt = (const int*)d_in[2];
    float* out = (float*)d_out;

    cudaFuncSetAttribute(k_sim_sym, cudaFuncAttributeMaxDynamicSharedMemorySize, SMEM_TOTAL);

    k_norm<<<N / 32, 256>>>(emb);
    k_sim_sym<<<148, 512, SMEM_TOTAL>>>(logits, tgt);
    k_clsfinal<<<CLS, DIM>>>();
    k_con<<<N / 16, 256>>>(tgt);
    k_final<<<1, 256>>>(out, out_size);
}

// round 14
// speedup vs baseline: 1.0822x; 1.0189x over previous
#include <cuda_runtime.h>
#include <cuda_fp16.h>
#include <math.h>
#include <stdint.h>

#define N 8192
#define CLS 8
#define DIM 256
#define INV_T 14.285714285714286f
#define EXP_SCALE 20.60992915555662f   /* (1/0.07) * log2(e) */
#define ALPHA 0.3f
#define LSM 0.1f
#define NT_ROW 64
#define NCHUNK 128

// ---------------- scratch ------------------------------------------------------------
__device__ float g_embn[N * DIM];
__device__ uint16_t g_embq[N * DIM / 2];
__device__ float g_clsum_part[NCHUNK * CLS * DIM];
__device__ float g_clcnt_part[NCHUNK * CLS];
__device__ float g_clsum[CLS * DIM];
__device__ float g_clcnt[CLS];
__device__ float g_Zp[N * NT_ROW];
__device__ float g_con[N];
__device__ float g_ce_part[16 * 16];

// ---------------- helpers ------------------------------------------------------------
__device__ __forceinline__ uint32_t smem_u32(const void* p) {
    uint32_t a;
    asm("{ .reg .u64 t; cvta.to.shared.u64 t, %1; cvt.u32.u64 %0, t; }" : "=r"(a) : "l"(p));
    return a;
}
__device__ __forceinline__ float ex2f(float x) {
    float y; asm("ex2.approx.f32 %0, %1;" : "=f"(y) : "f"(x)); return y;
}
__device__ __forceinline__ void cp16(uint32_t dst, const void* src) {
    asm volatile("cp.async.cg.shared.global [%0], [%1], 16;" :: "r"(dst), "l"(src));
}
#define CP_COMMIT() asm volatile("cp.async.commit_group;" ::: "memory")
#define CP_WAIT0()  asm volatile("cp.async.wait_group 0;" ::: "memory")

__device__ __forceinline__ void ldsm4(uint32_t& r0, uint32_t& r1, uint32_t& r2, uint32_t& r3,
                                      uint32_t addr) {
    asm volatile("ldmatrix.sync.aligned.m8n8.x4.shared.b16 {%0,%1,%2,%3}, [%4];"
                 : "=r"(r0), "=r"(r1), "=r"(r2), "=r"(r3) : "r"(addr));
}
__device__ __forceinline__ void mma_fp8(float* c, uint32_t a0, uint32_t a1, uint32_t a2,
                                        uint32_t a3, uint32_t b0, uint32_t b1) {
    asm volatile("mma.sync.aligned.m16n8k32.row.col.f32.e4m3.e4m3.f32 "
                 "{%0,%1,%2,%3}, {%4,%5,%6,%7}, {%8,%9}, {%0,%1,%2,%3};"
                 : "+f"(c[0]), "+f"(c[1]), "+f"(c[2]), "+f"(c[3])
                 : "r"(a0), "r"(a1), "r"(a2), "r"(a3), "r"(b0), "r"(b1));
}
__device__ __forceinline__ uint16_t f2e4m3x2(float hi, float lo) {
    uint16_t r;
    asm("cvt.rn.satfinite.e4m3x2.f32 %0, %1, %2;" : "=h"(r) : "f"(hi), "f"(lo));
    return r;
}
// e4m3 pair -> 2 floats (pure PTX; no half-type API dependence)
__device__ __forceinline__ float2 e4m3x2_to_f2(uint32_t p) {
    uint32_t h;
    float lo, hi;
    asm("cvt.rn.f16x2.e4m3x2 %0, %1;" : "=r"(h) : "h"((uint16_t)p));
    asm("{ .reg .f16 a, b; mov.b32 {a, b}, %2; cvt.f32.f16 %0, a; cvt.f32.f16 %1, b; }"
        : "=f"(lo), "=f"(hi) : "r"(h));
    return make_float2(lo, hi);
}

// ---------------- 1) normalize + fp8 convert (warp per row — R9 proven) --------------
__global__ void k_norm(const float* __restrict__ emb) {
    int w = threadIdx.x >> 5, lane = threadIdx.x & 31;
    int row = blockIdx.x * 8 + w;
    const float4* src = (const float4*)(emb + (size_t)row * DIM);
    float4 v0 = src[lane * 2], v1 = src[lane * 2 + 1];
    float ss = v0.x * v0.x + v0.y * v0.y + v0.z * v0.z + v0.w * v0.w +
               v1.x * v1.x + v1.y * v1.y + v1.z * v1.z + v1.w * v1.w;
#pragma unroll
    for (int off = 16; off > 0; off >>= 1) ss += __shfl_xor_sync(0xFFFFFFFF, ss, off);
    float inv = 1.0f / fmaxf(sqrtf(ss), 1e-12f);
    v0.x *= inv; v0.y *= inv; v0.z *= inv; v0.w *= inv;
    v1.x *= inv; v1.y *= inv; v1.z *= inv; v1.w *= inv;
    float4* dst = (float4*)(g_embn + (size_t)row * DIM);
    dst[lane * 2] = v0;
    dst[lane * 2 + 1] = v1;
    uint32_t u0 = (uint32_t)f2e4m3x2(v0.y, v0.x) | ((uint32_t)f2e4m3x2(v0.w, v0.z) << 16);
    uint32_t u1 = (uint32_t)f2e4m3x2(v1.y, v1.x) | ((uint32_t)f2e4m3x2(v1.w, v1.z) << 16);
    *(uint2*)(g_embq + (size_t)row * 128 + lane * 4) = make_uint2(u0, u1);
}

// ---------------- 2) HOT: symmetric Z + folded side jobs (identical to R9) -----------
#define SAB 272
#define A_BYTES (128 * SAB)
#define AS(p) ((p) * A_BYTES)
#define BS(b) ((2 + (b)) * A_BYTES)
#define RED_OFF (4 * A_BYTES)
#define RED_PAR 4096
#define SMEM_TOTAL (RED_OFF + 2 * RED_PAR)

__device__ __forceinline__ void load_tile_async(uint32_t sbase, int grow0, int tid) {
    const char* src = (const char*)g_embq + (size_t)grow0 * 256;
#pragma unroll
    for (int i = 0; i < 4; i++) {
        int idx = tid + i * 512;
        int row = idx >> 4, cb = idx & 15;
        cp16(sbase + row * SAB + cb * 16, src + (size_t)row * 256 + cb * 16);
    }
}

__global__ void __launch_bounds__(512, 1) k_sim_sym(const float* __restrict__ logits,
                                                   const int* __restrict__ tgt) {
    extern __shared__ char smem[];
    uint32_t sb = smem_u32(smem);
    int tid = threadIdx.x;
    int lane = tid & 31;
    int wid = tid >> 5;
    int wx = wid & 3;
    int wy = wid >> 2;
    int bid = blockIdx.x;

    int base = bid * 14 + (bid < 8 ? bid : 8);
    int cnt = 14 + (bid < 8 ? 1 : 0);

    int idx = base, I = 0;
    while (idx >= NT_ROW - I) { idx -= NT_ROW - I; I++; }
    int J = I + idx;

    int ap = 0;
    load_tile_async(sb + AS(0), I * 128, tid);
    if (J != I) load_tile_async(sb + BS(0), J * 128, tid);
    CP_COMMIT();

    if (bid >= 8 && bid < 72) {
        int half = tid >> 8;
        int d = tid & 255;
        int chunk = (bid - 8) * 2 + half;
        int i0 = chunk * 64;
        float a[CLS];
#pragma unroll
        for (int c = 0; c < CLS; c++) a[c] = 0.f;
        for (int k = 0; k < 64; k++) {
            int tg = tgt[i0 + k];
            float v = g_embn[(size_t)(i0 + k) * DIM + d];
#pragma unroll
            for (int c = 0; c < CLS; c++) a[c] += (tg == c) ? v : 0.f;
        }
#pragma unroll
        for (int c = 0; c < CLS; c++) g_clsum_part[(chunk * CLS + c) * DIM + d] = a[c];
        if (d == 0) {
            int cc[CLS];
#pragma unroll
            for (int c = 0; c < CLS; c++) cc[c] = 0;
            for (int k = 0; k < 64; k++) {
                int tg = tgt[i0 + k];
#pragma unroll
                for (int c = 0; c < CLS; c++) cc[c] += (tg == c);
            }
#pragma unroll
            for (int c = 0; c < CLS; c++) g_clcnt_part[chunk * CLS + c] = (float)cc[c];
        }
    } else if (bid >= 72 && bid < 88) {
        int chunk = bid - 72;
        int i = chunk * 512 + tid;
        const float4* p = (const float4*)(logits + (size_t)i * CLS);
        float4 u = p[0], w = p[1];
        float x[CLS] = {u.x, u.y, u.z, u.w, w.x, w.y, w.z, w.w};
        float m = x[0];
#pragma unroll
        for (int j = 1; j < CLS; j++) m = fmaxf(m, x[j]);
        float se = 0.f;
#pragma unroll
        for (int j = 0; j < CLS; j++) se += expf(x[j] - m);
        float lse = m + logf(se);
        int tg = tgt[i];
        float nll = lse - x[tg];
        float sx = 0.f;
#pragma unroll
        for (int j = 0; j < CLS; j++) sx += x[j];
        float smooth = lse - sx * (1.0f / CLS);
        float ce = (1.0f - LSM) * nll + LSM * smooth;
        float pt = expf(-ce);
        float omp = 1.0f - pt;
        float focal = omp * omp * ce;
#pragma unroll
        for (int off = 16; off > 0; off >>= 1)
            focal += __shfl_xor_sync(0xFFFFFFFF, focal, off);
        if (lane == 0) g_ce_part[chunk * 16 + wid] = focal;
    }

    CP_WAIT0();
    __syncthreads();

    uint32_t a_lane = (wy * 32 + (lane & 15)) * SAB + ((lane >> 4) << 4);
    uint32_t b_lane = ((lane & 7) + ((lane >> 4) << 3)) * SAB + (((lane >> 3) & 1) << 4) +
                      (wx * 32) * SAB;

    const float EXP_DIAG = expf(INV_T);
    int lrl0 = wy * 32 + (lane >> 2);
    int lcb0 = wx * 32 + (lane & 3) * 2;

    float prev[2][4][4];
    int Ip = 0, Jp = 0;
    bool dtp = false;

    for (int t = 0; t < cnt; t++) {
        int I1 = I, J1 = J + 1;
        if (J1 == NT_ROW) { I1 = I + 1; J1 = I1; }
        bool havenext = (t + 1 < cnt);
        int apn = ap;
        if (havenext) {
            if (I1 != I) {
                apn = ap ^ 1;
                load_tile_async(sb + AS(apn), I1 * 128, tid);
            }
            if (J1 != I1) {
                load_tile_async(sb + BS((t + 1) & 1), J1 * 128, tid);
            }
            CP_COMMIT();
        }

        bool dt = (I == J);
        uint32_t a_addr = sb + AS(ap) + a_lane;
        uint32_t bbuf = (dt ? (sb + AS(ap)) : (sb + BS(t & 1))) + b_lane;

        float acc[2][4][4];
#pragma unroll
        for (int mt = 0; mt < 2; mt++)
#pragma unroll
            for (int nt = 0; nt < 4; nt++)
#pragma unroll
                for (int q = 0; q < 4; q++) acc[mt][nt][q] = 0.f;

        float rlo[2] = {0.f, 0.f}, rhi[2] = {0.f, 0.f};
        float cp0[4] = {0.f, 0.f, 0.f, 0.f}, cp1[4] = {0.f, 0.f, 0.f, 0.f};

#pragma unroll
        for (int ks = 0; ks < 8; ks++) {
            uint32_t koff = ks * 32;
            uint32_t a0[4], a1[4];
            ldsm4(a0[0], a0[1], a0[2], a0[3], a_addr + koff);
            ldsm4(a1[0], a1[1], a1[2], a1[3], a_addr + 16 * SAB + koff);
            uint32_t bfr[2][4];
#pragma unroll
            for (int p = 0; p < 2; p++)
                ldsm4(bfr[p][0], bfr[p][1], bfr[p][2], bfr[p][3],
                      bbuf + (p * 16) * SAB + koff);
#pragma unroll
            for (int nt = 0; nt < 4; nt++) {
                uint32_t bb0 = bfr[nt >> 1][(nt & 1) * 2];
                uint32_t bb1 = bfr[nt >> 1][(nt & 1) * 2 + 1];
                mma_fp8(acc[0][nt], a0[0], a0[1], a0[2], a0[3], bb0, bb1);
                mma_fp8(acc[1][nt], a1[0], a1[1], a1[2], a1[3], bb0, bb1);
            }
            if (t > 0) {
                int mt = ks & 1, nt = ks >> 1;
                int lr = lrl0 + mt * 16;
                int lc = lcb0 + nt * 8;
                float v0 = (dtp && lc == lr)         ? EXP_DIAG : ex2f(prev[mt][nt][0] * EXP_SCALE);
                float v1 = (dtp && lc + 1 == lr)     ? EXP_DIAG : ex2f(prev[mt][nt][1] * EXP_SCALE);
                float v2 = (dtp && lc == lr + 8)     ? EXP_DIAG : ex2f(prev[mt][nt][2] * EXP_SCALE);
                float v3 = (dtp && lc + 1 == lr + 8) ? EXP_DIAG : ex2f(prev[mt][nt][3] * EXP_SCALE);
                rlo[mt] += v0 + v1;
                rhi[mt] += v2 + v3;
                cp0[nt] += v0 + v2;
                cp1[nt] += v1 + v3;
            }
        }

        if (t > 0) {
            float* red_row = (float*)(smem + RED_OFF + ((t - 1) & 1) * RED_PAR);
            float* red_col = red_row + 512;
#pragma unroll
            for (int mt = 0; mt < 2; mt++) {
                rlo[mt] += __shfl_xor_sync(0xFFFFFFFF, rlo[mt], 1);
                rlo[mt] += __shfl_xor_sync(0xFFFFFFFF, rlo[mt], 2);
                rhi[mt] += __shfl_xor_sync(0xFFFFFFFF, rhi[mt], 1);
                rhi[mt] += __shfl_xor_sync(0xFFFFFFFF, rhi[mt], 2);
            }
#pragma unroll
            for (int nt = 0; nt < 4; nt++) {
                cp0[nt] += __shfl_xor_sync(0xFFFFFFFF, cp0[nt], 4);
                cp0[nt] += __shfl_xor_sync(0xFFFFFFFF, cp0[nt], 8);
                cp0[nt] += __shfl_xor_sync(0xFFFFFFFF, cp0[nt], 16);
                cp1[nt] += __shfl_xor_sync(0xFFFFFFFF, cp1[nt], 4);
                cp1[nt] += __shfl_xor_sync(0xFFFFFFFF, cp1[nt], 8);
                cp1[nt] += __shfl_xor_sync(0xFFFFFFFF, cp1[nt], 16);
            }
            if ((lane & 3) == 0) {
#pragma unroll
                for (int mt = 0; mt < 2; mt++) {
                    int r = wy * 32 + mt * 16 + (lane >> 2);
                    red_row[r * 4 + wx] = rlo[mt];
                    red_row[(r + 8) * 4 + wx] = rhi[mt];
                }
            }
            if (lane < 4) {
#pragma unroll
                for (int nt = 0; nt < 4; nt++) {
                    int c = wx * 32 + nt * 8 + lane * 2;
                    red_col[c * 4 + wy] = cp0[nt];
                    red_col[(c + 1) * 4 + wy] = cp1[nt];
                }
            }
        }
        if (havenext) CP_WAIT0();
        __syncthreads();
        if (t > 0 && tid < 128) {
            float* red_row = (float*)(smem + RED_OFF + ((t - 1) & 1) * RED_PAR);
            float* red_col = red_row + 512;
            float rz = (red_row[tid * 4] + red_row[tid * 4 + 1]) +
                       (red_row[tid * 4 + 2] + red_row[tid * 4 + 3]);
            g_Zp[(size_t)(Ip * 128 + tid) * NT_ROW + Jp] = rz;
            if (!dtp) {
                float cz = (red_col[tid * 4] + red_col[tid * 4 + 1]) +
                           (red_col[tid * 4 + 2] + red_col[tid * 4 + 3]);
                g_Zp[(size_t)(Jp * 128 + tid) * NT_ROW + Ip] = cz;
            }
        }

#pragma unroll
        for (int mt = 0; mt < 2; mt++)
#pragma unroll
            for (int nt = 0; nt < 4; nt++)
#pragma unroll
                for (int q = 0; q < 4; q++) prev[mt][nt][q] = acc[mt][nt][q];
        Ip = I; Jp = J; dtp = (I == J);
        I = I1; J = J1; ap = apn;
    }

    // final epilogue for last tile
    {
        float rlo[2] = {0.f, 0.f}, rhi[2] = {0.f, 0.f};
        float cp0[4] = {0.f, 0.f, 0.f, 0.f}, cp1[4] = {0.f, 0.f, 0.f, 0.f};
#pragma unroll
        for (int ks = 0; ks < 8; ks++) {
            int mt = ks & 1, nt = ks >> 1;
            int lr = lrl0 + mt * 16;
            int lc = lcb0 + nt * 8;
            float v0 = (dtp && lc == lr)         ? EXP_DIAG : ex2f(prev[mt][nt][0] * EXP_SCALE);
            float v1 = (dtp && lc + 1 == lr)     ? EXP_DIAG : ex2f(prev[mt][nt][1] * EXP_SCALE);
            float v2 = (dtp && lc == lr + 8)     ? EXP_DIAG : ex2f(prev[mt][nt][2] * EXP_SCALE);
            float v3 = (dtp && lc + 1 == lr + 8) ? EXP_DIAG : ex2f(prev[mt][nt][3] * EXP_SCALE);
            rlo[mt] += v0 + v1;
            rhi[mt] += v2 + v3;
            cp0[nt] += v0 + v2;
            cp1[nt] += v1 + v3;
        }
        float* red_row = (float*)(smem + RED_OFF + ((cnt - 1) & 1) * RED_PAR);
        float* red_col = red_row + 512;
#pragma unroll
        for (int mt = 0; mt < 2; mt++) {
            rlo[mt] += __shfl_xor_sync(0xFFFFFFFF, rlo[mt], 1);
            rlo[mt] += __shfl_xor_sync(0xFFFFFFFF, rlo[mt], 2);
            rhi[mt] += __shfl_xor_sync(0xFFFFFFFF, rhi[mt], 1);
            rhi[mt] += __shfl_xor_sync(0xFFFFFFFF, rhi[mt], 2);
        }
#pragma unroll
        for (int nt = 0; nt < 4; nt++) {
            cp0[nt] += __shfl_xor_sync(0xFFFFFFFF, cp0[nt], 4);
            cp0[nt] += __shfl_xor_sync(0xFFFFFFFF, cp0[nt], 8);
            cp0[nt] += __shfl_xor_sync(0xFFFFFFFF, cp0[nt], 16);
            cp1[nt] += __shfl_xor_sync(0xFFFFFFFF, cp1[nt], 4);
            cp1[nt] += __shfl_xor_sync(0xFFFFFFFF, cp1[nt], 8);
            cp1[nt] += __shfl_xor_sync(0xFFFFFFFF, cp1[nt], 16);
        }
        if ((lane & 3) == 0) {
#pragma unroll
            for (int mt = 0; mt < 2; mt++) {
                int r = wy * 32 + mt * 16 + (lane >> 2);
                red_row[r * 4 + wx] = rlo[mt];
                red_row[(r + 8) * 4 + wx] = rhi[mt];
            }
        }
        if (lane < 4) {
#pragma unroll
            for (int nt = 0; nt < 4; nt++) {
                int c = wx * 32 + nt * 8 + lane * 2;
                red_col[c * 4 + wy] = cp0[nt];
                red_col[(c + 1) * 4 + wy] = cp1[nt];
            }
        }
        __syncthreads();
        if (tid < 128) {
            float rz = (red_row[tid * 4] + red_row[tid * 4 + 1]) +
                       (red_row[tid * 4 + 2] + red_row[tid * 4 + 3]);
            g_Zp[(size_t)(Ip * 128 + tid) * NT_ROW + Jp] = rz;
            if (!dtp) {
                float cz = (red_col[tid * 4] + red_col[tid * 4 + 1]) +
                           (red_col[tid * 4 + 2] + red_col[tid * 4 + 3]);
                g_Zp[(size_t)(Jp * 128 + tid) * NT_ROW + Ip] = cz;
            }
        }
    }
}

// ---------------- 3) class-sum finalize ----------------------------------------------
__global__ void k_clsfinal() {
    int c = blockIdx.x, d = threadIdx.x;
    float s = 0.f;
    for (int b = 0; b < NCHUNK; b++) s += g_clsum_part[(b * CLS + c) * DIM + d];
    g_clsum[c * DIM + d] = s;
    if (d == 0) {
        float cn = 0.f;
        for (int b = 0; b < NCHUNK; b++) cn += g_clcnt_part[b * CLS + c];
        g_clcnt[c] = cn;
    }
}

// ---------------- 4) per-row contrastive: R9 shape, fp8 embedding reads --------------
__global__ void k_con(const int* __restrict__ tgt) {
    int w = threadIdx.x >> 5, lane = threadIdx.x & 31;
    int row = blockIdx.x * 8 + w;
    int t = tgt[row];
    float zs = g_Zp[(size_t)row * NT_ROW + lane] + g_Zp[(size_t)row * NT_ROW + lane + 32];
    // fp8 embedding: lane handles values [lane*8, lane*8+8) = uint2 at row*128 + lane*4
    uint2 q = *(const uint2*)(g_embq + (size_t)row * 128 + lane * 4);
    const float4* sc = (const float4*)&g_clsum[t * DIM];
    float4 c0 = sc[lane * 2], c1 = sc[lane * 2 + 1];

    float2 e0 = e4m3x2_to_f2(q.x & 0xFFFFu);
    float2 e1 = e4m3x2_to_f2(q.x >> 16);
    float2 e2 = e4m3x2_to_f2(q.y & 0xFFFFu);
    float2 e3 = e4m3x2_to_f2(q.y >> 16);

    float dot = e0.x * c0.x + e0.y * c0.y + e1.x * c0.z + e1.y * c0.w +
                e2.x * c1.x + e2.y * c1.y + e3.x * c1.z + e3.y * c1.w;
#pragma unroll
    for (int off = 16; off > 0; off >>= 1) {
        dot += __shfl_xor_sync(0xFFFFFFFF, dot, off);
        zs += __shfl_xor_sync(0xFFFFFFFF, zs, off);
    }
    if (lane == 0) {
        float logZ = logf(zs + 1e-8f);
        float npos = g_clcnt[t] - 1.0f;
        float msum = (dot - 1.0f) * INV_T;
        g_con[row] = (npos * logZ - msum) / fmaxf(npos, 1.0f);
    }
}

// ---------------- 5) final reduction -------------------------------------------------
__global__ void k_final(float* __restrict__ out, int out_size) {
    __shared__ float s[256];
    int t = threadIdx.x;

    float cs = 0.f;
    for (int i = t; i < N; i += 256) cs += g_con[i];
    s[t] = cs;
    __syncthreads();
    for (int off = 128; off > 0; off >>= 1) {
        if (t < off) s[t] += s[t + off];
        __syncthreads();
    }
    __shared__ float con_sum;
    if (t == 0) con_sum = s[0];
    __syncthreads();

    s[t] = g_ce_part[t];
    __syncthreads();
    for (int off = 128; off > 0; off >>= 1) {
        if (t < off) s[t] += s[t + off];
        __syncthreads();
    }
    if (t == 0) {
        float ce_mean = s[0] * (1.0f / N);
        float con_mean = con_sum * (1.0f / N);
        out[0] = ce_mean + ALPHA * con_mean;
        if (out_size > 1) out[1] = ce_mean;
        if (out_size > 2) out[2] = con_mean;
    }
}

// ---------------- launcher ----------------------------------------------------------
extern "C" void kernel_launch(void* const* d_in, const int* in_sizes, int n_in,
                              void* d_out, int out_size) {
    const float* logits = (const float*)d_in[0];
    const float* emb = (const float*)d_in[1];
    const int* tgt = (const int*)d_in[2];
    float* out = (float*)d_out;

    cudaFuncSetAttribute(k_sim_sym, cudaFuncAttributeMaxDynamicSharedMemorySize, SMEM_TOTAL);

    k_norm<<<N / 8, 256>>>(emb);
    k_sim_sym<<<148, 512, SMEM_TOTAL>>>(logits, tgt);
    k_clsfinal<<<CLS, DIM>>>();
    k_con<<<N / 8, 256>>>(tgt);
    k_final<<<1, 256>>>(out, out_size);
}